// round 6
// baseline (speedup 1.0000x reference)
#include <cuda_runtime.h>
#include <cstdint>

// Model_25855703122577: inputs [8192,784,1] f32, W_ih[30,1], W_hh[30,30],
// b_mod[30], W_lin[10,30], b_lin[10] -> out [8192,10] f32
#define RB    8192
#define RT    784
#define RH    30
#define RC    10
#define GRP   4        // lanes per batch element
#define RREG  4        // rows per lane held in registers
#define RSM   4        // rows per lane streamed from smem
#define RPT   8        // total rows per lane (4*8 = 32 >= 30)
#define KP    15       // k-pairs for register rows (exact)
#define NCH   8        // 16B h-chunks (32 floats incl. maintained-zero pads)
#define TPB   32       // one warp per block
#define SLOTS 8        // batches per warp
#define HSTR  36       // floats per h slot (144B: 16B-aligned slot bases)

typedef unsigned long long u64;

__device__ __forceinline__ u64 fmul2(u64 a, u64 b) {
    u64 d; asm("mul.rn.f32x2 %0, %1, %2;" : "=l"(d) : "l"(a), "l"(b)); return d;
}
__device__ __forceinline__ u64 ffma2(u64 a, u64 b, u64 c) {
    u64 d; asm("fma.rn.f32x2 %0, %1, %2, %3;" : "=l"(d) : "l"(a), "l"(b), "l"(c)); return d;
}
__device__ __forceinline__ void unpack2(u64 v, float& lo, float& hi) {
    asm("mov.b64 {%0, %1}, %2;" : "=f"(lo), "=f"(hi) : "l"(v));
}
__device__ __forceinline__ float modrelu(float z, float b) {
    float m = fmaxf(fabsf(z) + b, 0.0f);
    float s = copysignf(m, z);
    return (z == 0.0f) ? 0.0f : s;
}

struct Smem {
    alignas(16) float hbuf[2][SLOTS][HSTR];
    alignas(16) float wsm[RSM * 8 * GRP * 4];  // [rr][p2][g] 16B chunks
};

// One recurrence step: 8 rows for this lane's batch.
// Rows 0..3 weights in regs (15 pairs), rows 4..7 from smem (16 pairs, padded).
__device__ __forceinline__ void rnn_step(
    float x,
    const u64 (&w)[RREG][KP],
    const float (&wih)[RPT],
    const float (&bm)[RPT],
    const float* __restrict__ wsm_g,          // &wsm[0] + g*16B chunk base
    const float* __restrict__ hsrc,           // slot base, 32 floats
    float* __restrict__ hdst)                 // slot base + 8*g floats
{
    const ulonglong2* hp = reinterpret_cast<const ulonglong2*>(hsrc);
    const ulonglong2* wp = reinterpret_cast<const ulonglong2*>(wsm_g);

    u64 acc[RPT];

    // p2 = 0 : start all 8 chains
    {
        const ulonglong2 hc = hp[0];
#pragma unroll
        for (int r = 0; r < RREG; r++) {
            acc[r] = fmul2(w[r][0], hc.x);
            acc[r] = ffma2(w[r][1], hc.y, acc[r]);
        }
#pragma unroll
        for (int rr = 0; rr < RSM; rr++) {
            const ulonglong2 wc = wp[(rr * 8 + 0) * GRP];   // [rr][0][g]
            acc[RREG + rr] = fmul2(wc.x, hc.x);
            acc[RREG + rr] = ffma2(wc.y, hc.y, acc[RREG + rr]);
        }
    }
#pragma unroll
    for (int p2 = 1; p2 < NCH; p2++) {
        const ulonglong2 hc = hp[p2];
#pragma unroll
        for (int r = 0; r < RREG; r++) {
            acc[r] = ffma2(w[r][2 * p2], hc.x, acc[r]);
            if (2 * p2 + 1 < KP)
                acc[r] = ffma2(w[r][2 * p2 + 1], hc.y, acc[r]);
        }
#pragma unroll
        for (int rr = 0; rr < RSM; rr++) {
            const ulonglong2 wc = wp[(rr * 8 + p2) * GRP];  // [rr][p2][g]
            acc[RREG + rr] = ffma2(wc.x, hc.x, acc[RREG + rr]);
            acc[RREG + rr] = ffma2(wc.y, hc.y, acc[RREG + rr]);
        }
    }

    float hv[RPT];
#pragma unroll
    for (int r = 0; r < RPT; r++) {
        float lo, hi;
        unpack2(acc[r], lo, hi);
        float z = fmaf(x, wih[r], lo + hi);
        hv[r] = modrelu(z, bm[r]);
    }
    reinterpret_cast<float4*>(hdst)[0] = make_float4(hv[0], hv[1], hv[2], hv[3]);
    reinterpret_cast<float4*>(hdst)[1] = make_float4(hv[4], hv[5], hv[6], hv[7]);
    __syncwarp();
}

extern "C" __global__ void __launch_bounds__(TPB)
rnn_modrelu_kernel(const float* __restrict__ inputs,  // [B, T]
                   const float* __restrict__ W_ih,    // [H]
                   const float* __restrict__ W_hh,    // [H, H]
                   const float* __restrict__ b_mod,   // [H]
                   const float* __restrict__ W_lin,   // [C, H]
                   const float* __restrict__ b_lin,   // [C]
                   float* __restrict__ out)           // [B, C]
{
    __shared__ Smem sm;

    const int tid = threadIdx.x;       // 0..31
    const int g   = tid & (GRP - 1);   // 0..3 : row-slice within batch
    const int s   = tid >> 2;          // 0..7 : batch slot
    const int b   = blockIdx.x * SLOTS + s;

    // ---- stage smem weight tile: rows 8g+4+rr, layout [rr][p2][g] ----
#pragma unroll
    for (int e = tid; e < RSM * 8 * GRP; e += TPB) {
        const int eg  = e & 3;
        const int ep2 = (e >> 2) & 7;
        const int err = e >> 5;
        const int row = 8 * eg + RREG + err;
        float v[4];
#pragma unroll
        for (int q = 0; q < 4; q++) {
            const int k = 4 * ep2 + q;
            v[q] = (row < RH && k < RH) ? W_hh[row * RH + k] : 0.0f;
        }
        reinterpret_cast<float4*>(sm.wsm)[e] = make_float4(v[0], v[1], v[2], v[3]);
    }

    // ---- register weight rows 8g..8g+3 (always < 30 for g<=3: 24..27 max) ----
    u64 w[RREG][KP];
    float wih[RPT], bm[RPT];
#pragma unroll
    for (int r = 0; r < RREG; r++) {
        const int row = 8 * g + r;
        const u64* wr = reinterpret_cast<const u64*>(W_hh + row * RH);
#pragma unroll
        for (int p = 0; p < KP; p++) w[r][p] = wr[p];
    }
#pragma unroll
    for (int r = 0; r < RPT; r++) {
        const int row = 8 * g + r;
        wih[r] = (row < RH) ? W_ih[row]  : 0.0f;
        bm[r]  = (row < RH) ? b_mod[row] : 0.0f;
    }

    // h0 = 0 (each lane zeroes its 8 floats; pads rows 30,31 stay 0 forever)
    reinterpret_cast<float4*>(&sm.hbuf[0][s][8 * g])[0] = make_float4(0, 0, 0, 0);
    reinterpret_cast<float4*>(&sm.hbuf[0][s][8 * g])[1] = make_float4(0, 0, 0, 0);
    __syncwarp();

    const float* wsm_g = sm.wsm + g * 4;          // g-th 16B chunk column
    const float* xr = inputs + (size_t)b * RT;
    float* dst = &sm.hbuf[0][s][0];               // rebased per step below

#pragma unroll 1
    for (int t0 = 0; t0 < RT; t0 += 4) {
        const float4 x4 = *reinterpret_cast<const float4*>(xr + t0);
        rnn_step(x4.x, w, wih, bm, wsm_g, &sm.hbuf[0][s][0], &sm.hbuf[1][s][8 * g]);
        rnn_step(x4.y, w, wih, bm, wsm_g, &sm.hbuf[1][s][0], &sm.hbuf[0][s][8 * g]);
        rnn_step(x4.z, w, wih, bm, wsm_g, &sm.hbuf[0][s][0], &sm.hbuf[1][s][8 * g]);
        rnn_step(x4.w, w, wih, bm, wsm_g, &sm.hbuf[1][s][0], &sm.hbuf[0][s][8 * g]);
    }
    // T=784: even number of ping-pongs -> final h in buffer 0

    // ---- fused classifier: out[b][c] = h . W_lin[c] + b_lin[c] ----
    const float* hf = &sm.hbuf[0][s][0];
#pragma unroll 1
    for (int c = g; c < RC; c += GRP) {
        float acc = b_lin[c];
        const float* wl = W_lin + c * RH;
#pragma unroll
        for (int k = 0; k < RH; k++) acc = fmaf(hf[k], wl[k], acc);
        out[(size_t)b * RC + c] = acc;
    }
    (void)dst;
}

extern "C" void kernel_launch(void* const* d_in, const int* in_sizes, int n_in,
                              void* d_out, int out_size) {
    const float* inputs = (const float*)d_in[0];
    const float* W_ih   = (const float*)d_in[1];
    const float* W_hh   = (const float*)d_in[2];
    const float* b_mod  = (const float*)d_in[3];
    const float* W_lin  = (const float*)d_in[4];
    const float* b_lin  = (const float*)d_in[5];
    float* out = (float*)d_out;

    dim3 grid(RB / SLOTS);   // 1024 one-warp blocks, ~7/SM: single wave for sure
    dim3 block(TPB);
    rnn_modrelu_kernel<<<grid, block>>>(inputs, W_ih, W_hh, b_mod,
                                        W_lin, b_lin, out);
}